// round 11
// baseline (speedup 1.0000x reference)
#include <cuda_runtime.h>
#include <cuda_bf16.h>
#include <cstdint>
#include <cstddef>

using bf16 = __nv_bfloat16;

// Problem constants (fixed by metadata)
static constexpr int  DIM  = 4096;
static constexpr int  HIDN = 16384;
static constexpr int  MTOK = 4096;                 // 2 * 2048 tokens
static constexpr long NW   = (long)DIM * HIDN;     // 67,108,864 (all three weight mats)
static constexpr long NX   = (long)MTOK * DIM;     // 16,777,216
static constexpr long NH   = (long)MTOK * HIDN;    // 67,108,864

// ---------------- scratch (device globals: no cudaMalloc allowed) ----------------
__device__ double g_abs_sum[3];

__device__ __align__(16) bf16  g_wq_gate[NW];
__device__ __align__(16) bf16  g_wq_up[NW];
__device__ __align__(16) bf16  g_wq_down[NW];
__device__ __align__(16) bf16  g_x_hi[NX];
__device__ __align__(16) bf16  g_x_lo[NX];
__device__ __align__(16) float g_gate[NH];
__device__ __align__(16) float g_up[NH];
__device__ __align__(16) bf16  g_h_hi[NH];
__device__ __align__(16) bf16  g_h_lo[NH];

// ---------------- small utility kernels ----------------
__global__ void zero_sums_kernel() {
    if (threadIdx.x < 3) g_abs_sum[threadIdx.x] = 0.0;
}

// fp64 abs-sum reduction (threshold must be near-exact; see theory)
__global__ void absum_kernel(const float* __restrict__ w, long n, int slot) {
    long nv = n >> 2;
    long stride = (long)gridDim.x * blockDim.x;
    double s = 0.0;
    for (long i = (long)blockIdx.x * blockDim.x + threadIdx.x; i < nv; i += stride) {
        float4 v = reinterpret_cast<const float4*>(w)[i];
        s += (double)fabsf(v.x) + (double)fabsf(v.y) +
             (double)fabsf(v.z) + (double)fabsf(v.w);
    }
    #pragma unroll
    for (int o = 16; o > 0; o >>= 1) s += __shfl_down_sync(0xffffffffu, s, o);
    __shared__ double red[8];
    int lane = threadIdx.x & 31, wid = threadIdx.x >> 5;
    if (lane == 0) red[wid] = s;
    __syncthreads();
    if (threadIdx.x == 0) {
        double t = 0.0;
        #pragma unroll
        for (int i = 0; i < 8; i++) t += red[i];
        atomicAdd(&g_abs_sum[slot], t);
    }
}

// ternary quantize: wq = sign(w) * (|w| > mean(|w|)*0.7), stored as bf16 {-1,0,1}
__global__ void quant_kernel(const float* __restrict__ w, bf16* __restrict__ q,
                             long n, int slot) {
    float thr = (float)(g_abs_sum[slot] * (0.7 / (double)n));
    long i = (long)blockIdx.x * blockDim.x + threadIdx.x;
    long nv = n >> 2;
    if (i >= nv) return;
    float4 v = reinterpret_cast<const float4*>(w)[i];
    float vv[4] = {v.x, v.y, v.z, v.w};
    unsigned short r[4];
    #pragma unroll
    for (int j = 0; j < 4; j++) {
        float a = fabsf(vv[j]);
        r[j] = (a > thr) ? (vv[j] > 0.f ? (unsigned short)0x3F80u
                                        : (unsigned short)0xBF80u)
                         : (unsigned short)0u;   // bf16 +1 / -1 / 0
    }
    reinterpret_cast<ushort4*>(q)[i] = make_ushort4(r[0], r[1], r[2], r[3]);
}

// split fp32 into bf16 hi + lo (two-term Dekker-style split)
__global__ void split_kernel(const float* __restrict__ x,
                             bf16* __restrict__ hi, bf16* __restrict__ lo, long n) {
    long i = (long)blockIdx.x * blockDim.x + threadIdx.x;
    long nv = n >> 2;
    if (i >= nv) return;
    float4 v = reinterpret_cast<const float4*>(x)[i];
    float vv[4] = {v.x, v.y, v.z, v.w};
    unsigned short rh[4], rl[4];
    #pragma unroll
    for (int j = 0; j < 4; j++) {
        bf16 h = __float2bfloat16(vv[j]);
        bf16 l = __float2bfloat16(vv[j] - __bfloat162float(h));
        rh[j] = __bfloat16_as_ushort(h);
        rl[j] = __bfloat16_as_ushort(l);
    }
    reinterpret_cast<ushort4*>(hi)[i] = make_ushort4(rh[0], rh[1], rh[2], rh[3]);
    reinterpret_cast<ushort4*>(lo)[i] = make_ushort4(rl[0], rl[1], rl[2], rl[3]);
}

// hidden = silu(gate) * up, split into bf16 hi/lo
__global__ void swiglu_kernel(const float* __restrict__ gate, const float* __restrict__ up,
                              bf16* __restrict__ hhi, bf16* __restrict__ hlo, long n) {
    long i = (long)blockIdx.x * blockDim.x + threadIdx.x;
    long nv = n >> 2;
    if (i >= nv) return;
    float4 g4 = reinterpret_cast<const float4*>(gate)[i];
    float4 u4 = reinterpret_cast<const float4*>(up)[i];
    float gg[4] = {g4.x, g4.y, g4.z, g4.w};
    float uu[4] = {u4.x, u4.y, u4.z, u4.w};
    unsigned short rh[4], rl[4];
    #pragma unroll
    for (int j = 0; j < 4; j++) {
        float g = gg[j];
        float s = 1.0f / (1.0f + expf(-g));
        float h = g * s * uu[j];
        bf16 hh = __float2bfloat16(h);
        bf16 ll = __float2bfloat16(h - __bfloat162float(hh));
        rh[j] = __bfloat16_as_ushort(hh);
        rl[j] = __bfloat16_as_ushort(ll);
    }
    reinterpret_cast<ushort4*>(hhi)[i] = make_ushort4(rh[0], rh[1], rh[2], rh[3]);
    reinterpret_cast<ushort4*>(hlo)[i] = make_ushort4(rl[0], rl[1], rl[2], rl[3]);
}

// ---------------- GEMM: C[M,N] = (Ahi+Alo)[M,K] * B[N,K]^T, epilogue *scale[n] ----------------
static constexpr int BM = 128;
static constexpr int BN = 128;
static constexpr int BK = 32;
static constexpr int SSTRIDE = 40;  // bf16 per smem row (pad: conflict-free frag LDS)
static constexpr int SMEM_BYTES = 6 * BM * SSTRIDE * 2;  // 61440 (Ah,Al,B double-buffered)

__device__ __forceinline__ void cp_async16(uint32_t saddr, const void* gptr) {
    asm volatile("cp.async.cg.shared.global [%0], [%1], 16;\n"
                 :: "r"(saddr), "l"(gptr) : "memory");
}
__device__ __forceinline__ void cp_commit() {
    asm volatile("cp.async.commit_group;\n" ::: "memory");
}
template <int N_>
__device__ __forceinline__ void cp_wait() {
    asm volatile("cp.async.wait_group %0;\n" :: "n"(N_) : "memory");
}

#define MMA_BF16(d, a, b)                                                         \
    asm volatile(                                                                 \
        "mma.sync.aligned.m16n8k16.row.col.f32.bf16.bf16.f32 "                    \
        "{%0,%1,%2,%3},{%4,%5,%6,%7},{%8,%9},{%0,%1,%2,%3};"                      \
        : "+f"(d[0]), "+f"(d[1]), "+f"(d[2]), "+f"(d[3])                          \
        : "r"(a[0]), "r"(a[1]), "r"(a[2]), "r"(a[3]), "r"(b[0]), "r"(b[1]))

__global__ void __launch_bounds__(256, 2)
gemm_bsplit(const bf16* __restrict__ Ah, const bf16* __restrict__ Al,
            const bf16* __restrict__ B, const float* __restrict__ scale,
            float* __restrict__ C, int M, int N, int K) {
    extern __shared__ bf16 smem[];
    bf16* sAh = smem;
    bf16* sAl = smem + 2 * BM * SSTRIDE;
    bf16* sB  = smem + 4 * BM * SSTRIDE;

    // tile swizzle for L2 reuse (GROUP_M rows of tiles per wave)
    int grid_m = M / BM, grid_n = N / BN;
    const int GROUP = 8;
    int pid = blockIdx.x;
    int width = GROUP * grid_n;
    int group_id = pid / width;
    int group_size = min(grid_m - group_id * GROUP, GROUP);
    int pid_m = group_id * GROUP + (pid % group_size);
    int pid_n = (pid % width) / group_size;

    int tid = threadIdx.x;
    int lane = tid & 31, warp = tid >> 5;
    int warp_m = warp & 1, warp_n = warp >> 1;   // 2 x 4 warp grid
    int gr = lane >> 2, tc = lane & 3;

    // cp.async mapping: 256 threads cover 128 rows x 4 sixteen-byte chunks, twice
    int lr = tid >> 2;   // rows 0..63 (second pass +64)
    int lq = tid & 3;    // 16B chunk within row

    const bf16* gAh = Ah + (size_t)pid_m * BM * K;
    const bf16* gAl = Al + (size_t)pid_m * BM * K;
    const bf16* gB  = B  + (size_t)pid_n * BN * K;

    uint32_t sbase = (uint32_t)__cvta_generic_to_shared(smem);

    auto load_stage = [&](int s, int kt) {
        int k0 = kt * BK;
        uint32_t dAh = sbase + (uint32_t)(s * BM * SSTRIDE * 2);
        uint32_t dAl = dAh + (uint32_t)(2 * BM * SSTRIDE * 2);
        uint32_t dB  = dAh + (uint32_t)(4 * BM * SSTRIDE * 2);
        #pragma unroll
        for (int h = 0; h < 2; ++h) {
            int r = lr + h * 64;
            uint32_t doff = (uint32_t)(r * SSTRIDE + lq * 8) * 2;
            size_t goff = (size_t)r * K + k0 + lq * 8;
            cp_async16(dAh + doff, gAh + goff);
            cp_async16(dAl + doff, gAl + goff);
            cp_async16(dB  + doff, gB  + goff);
        }
    };

    float acc[4][4][4];
    #pragma unroll
    for (int i = 0; i < 4; i++)
        #pragma unroll
        for (int j = 0; j < 4; j++)
            #pragma unroll
            for (int k = 0; k < 4; k++) acc[i][j][k] = 0.f;

    int KT = K / BK;
    load_stage(0, 0);
    cp_commit();

    for (int kt = 0; kt < KT; ++kt) {
        if (kt + 1 < KT) {
            load_stage((kt + 1) & 1, kt + 1);
            cp_commit();
            cp_wait<1>();
        } else {
            cp_wait<0>();
        }
        __syncthreads();

        int s = kt & 1;
        const bf16* pAh = sAh + s * BM * SSTRIDE;
        const bf16* pAl = sAl + s * BM * SSTRIDE;
        const bf16* pB  = sB  + s * BM * SSTRIDE;

        #pragma unroll
        for (int kc = 0; kc < 2; ++kc) {
            int kb = kc * 16 + tc * 2;
            uint32_t bfr[4][2];
            #pragma unroll
            for (int ni = 0; ni < 4; ++ni) {
                const bf16* p = pB + (warp_n * 32 + ni * 8 + gr) * SSTRIDE + kb;
                bfr[ni][0] = *reinterpret_cast<const uint32_t*>(p);
                bfr[ni][1] = *reinterpret_cast<const uint32_t*>(p + 8);
            }
            uint32_t af[4][4];
            // hi pass
            #pragma unroll
            for (int mi = 0; mi < 4; ++mi) {
                const bf16* p = pAh + (warp_m * 64 + mi * 16 + gr) * SSTRIDE + kb;
                af[mi][0] = *reinterpret_cast<const uint32_t*>(p);
                af[mi][1] = *reinterpret_cast<const uint32_t*>(p + 8 * SSTRIDE);
                af[mi][2] = *reinterpret_cast<const uint32_t*>(p + 8);
                af[mi][3] = *reinterpret_cast<const uint32_t*>(p + 8 * SSTRIDE + 8);
            }
            #pragma unroll
            for (int mi = 0; mi < 4; ++mi)
                #pragma unroll
                for (int ni = 0; ni < 4; ++ni)
                    MMA_BF16(acc[mi][ni], af[mi], bfr[ni]);
            // lo pass (reuse B fragments)
            #pragma unroll
            for (int mi = 0; mi < 4; ++mi) {
                const bf16* p = pAl + (warp_m * 64 + mi * 16 + gr) * SSTRIDE + kb;
                af[mi][0] = *reinterpret_cast<const uint32_t*>(p);
                af[mi][1] = *reinterpret_cast<const uint32_t*>(p + 8 * SSTRIDE);
                af[mi][2] = *reinterpret_cast<const uint32_t*>(p + 8);
                af[mi][3] = *reinterpret_cast<const uint32_t*>(p + 8 * SSTRIDE + 8);
            }
            #pragma unroll
            for (int mi = 0; mi < 4; ++mi)
                #pragma unroll
                for (int ni = 0; ni < 4; ++ni)
                    MMA_BF16(acc[mi][ni], af[mi], bfr[ni]);
        }
        __syncthreads();
    }

    // epilogue: C[m,n] = acc * scale[n]
    #pragma unroll
    for (int ni = 0; ni < 4; ++ni) {
        int n0 = pid_n * BN + warp_n * 32 + ni * 8 + tc * 2;
        float s0 = scale[n0], s1 = scale[n0 + 1];
        #pragma unroll
        for (int mi = 0; mi < 4; ++mi) {
            int m0 = pid_m * BM + warp_m * 64 + mi * 16 + gr;
            float2 v0 = make_float2(acc[mi][ni][0] * s0, acc[mi][ni][1] * s1);
            float2 v1 = make_float2(acc[mi][ni][2] * s0, acc[mi][ni][3] * s1);
            *reinterpret_cast<float2*>(&C[(size_t)m0 * N + n0]) = v0;
            *reinterpret_cast<float2*>(&C[(size_t)(m0 + 8) * N + n0]) = v1;
        }
    }
}

// ---------------- launcher ----------------
extern "C" void kernel_launch(void* const* d_in, const int* in_sizes, int n_in,
                              void* d_out, int out_size) {
    const float* x          = (const float*)d_in[0];
    const float* gate_w     = (const float*)d_in[1];
    const float* gate_scale = (const float*)d_in[2];
    const float* up_w       = (const float*)d_in[3];
    const float* up_scale   = (const float*)d_in[4];
    const float* down_w     = (const float*)d_in[5];
    const float* down_scale = (const float*)d_in[6];
    float* out = (float*)d_out;
    (void)in_sizes; (void)n_in; (void)out_size;

    void *p_wq_g, *p_wq_u, *p_wq_d, *p_xh, *p_xl, *p_gate, *p_up, *p_hh, *p_hl;
    cudaGetSymbolAddress(&p_wq_g, g_wq_gate);
    cudaGetSymbolAddress(&p_wq_u, g_wq_up);
    cudaGetSymbolAddress(&p_wq_d, g_wq_down);
    cudaGetSymbolAddress(&p_xh,   g_x_hi);
    cudaGetSymbolAddress(&p_xl,   g_x_lo);
    cudaGetSymbolAddress(&p_gate, g_gate);
    cudaGetSymbolAddress(&p_up,   g_up);
    cudaGetSymbolAddress(&p_hh,   g_h_hi);
    cudaGetSymbolAddress(&p_hl,   g_h_lo);

    cudaFuncSetAttribute(gemm_bsplit, cudaFuncAttributeMaxDynamicSharedMemorySize,
                         SMEM_BYTES);

    // 1) thresholds (fp64-accurate mean of |w|)
    zero_sums_kernel<<<1, 32>>>();
    absum_kernel<<<2048, 256>>>(gate_w, NW, 0);
    absum_kernel<<<2048, 256>>>(up_w,   NW, 1);
    absum_kernel<<<2048, 256>>>(down_w, NW, 2);

    // 2) ternary-quantize weights into bf16 (exact)
    unsigned qgrid = (unsigned)(NW / 4 / 256);
    quant_kernel<<<qgrid, 256>>>(gate_w, (bf16*)p_wq_g, NW, 0);
    quant_kernel<<<qgrid, 256>>>(up_w,   (bf16*)p_wq_u, NW, 1);
    quant_kernel<<<qgrid, 256>>>(down_w, (bf16*)p_wq_d, NW, 2);

    // 3) split activations into bf16 hi/lo
    split_kernel<<<(unsigned)(NX / 4 / 256), 256>>>(x, (bf16*)p_xh, (bf16*)p_xl, NX);

    // 4) gate / up GEMMs  (M=4096, N=16384, K=4096)
    unsigned grid1 = (unsigned)((MTOK / BM) * (HIDN / BN));
    gemm_bsplit<<<grid1, 256, SMEM_BYTES>>>((const bf16*)p_xh, (const bf16*)p_xl,
                                            (const bf16*)p_wq_g, gate_scale,
                                            (float*)p_gate, MTOK, HIDN, DIM);
    gemm_bsplit<<<grid1, 256, SMEM_BYTES>>>((const bf16*)p_xh, (const bf16*)p_xl,
                                            (const bf16*)p_wq_u, up_scale,
                                            (float*)p_up, MTOK, HIDN, DIM);

    // 5) silu(gate)*up, split to bf16 hi/lo
    swiglu_kernel<<<(unsigned)(NH / 4 / 256), 256>>>((const float*)p_gate,
                                                     (const float*)p_up,
                                                     (bf16*)p_hh, (bf16*)p_hl, NH);

    // 6) down GEMM straight into d_out  (M=4096, N=4096, K=16384)
    unsigned grid2 = (unsigned)((MTOK / BM) * (DIM / BN));
    gemm_bsplit<<<grid2, 256, SMEM_BYTES>>>((const bf16*)p_hh, (const bf16*)p_hl,
                                            (const bf16*)p_wq_d, down_scale,
                                            out, MTOK, DIM, HIDN);
}

// round 12
// speedup vs baseline: 1.5107x; 1.5107x over previous
#include <cuda_runtime.h>
#include <cuda_fp16.h>
#include <cstdint>
#include <cstddef>

using f16 = __half;

// Problem constants (fixed by metadata)
static constexpr int  DIM  = 4096;
static constexpr int  HIDN = 16384;
static constexpr int  MTOK = 4096;                 // 2 * 2048 tokens
static constexpr long NW   = (long)DIM * HIDN;     // 67,108,864
static constexpr long NX   = (long)MTOK * DIM;     // 16,777,216
static constexpr long NH   = (long)MTOK * HIDN;    // 67,108,864

// ---------------- scratch (device globals: no cudaMalloc allowed) ----------------
__device__ double g_abs_sum[3];

__device__ __align__(16) f16   g_wq_gate[NW];
__device__ __align__(16) f16   g_wq_up[NW];
__device__ __align__(16) f16   g_wq_down[NW];
__device__ __align__(16) f16   g_x16[NX];
__device__ __align__(16) float g_gate[NH];
__device__ __align__(16) float g_up[NH];
__device__ __align__(16) f16   g_h16[NH];

// ---------------- small utility kernels ----------------
__global__ void zero_sums_kernel() {
    if (threadIdx.x < 3) g_abs_sum[threadIdx.x] = 0.0;
}

// abs-sum: fp32 inner chunks (32 elems), fp64 outer accumulation.
// Threshold rel-err ~1e-8 — below JAX's own fp32-mean rounding noise.
__global__ void absum_kernel(const float* __restrict__ w, long n, int slot) {
    long nv = n >> 2;
    long stride = (long)gridDim.x * blockDim.x;
    long i0 = (long)blockIdx.x * blockDim.x + threadIdx.x;
    double acc = 0.0;
    for (long base = i0; base < nv; base += stride * 8) {
        float s = 0.f;
        #pragma unroll
        for (int j = 0; j < 8; j++) {
            long i = base + (long)j * stride;
            if (i < nv) {
                float4 v = reinterpret_cast<const float4*>(w)[i];
                s += fabsf(v.x) + fabsf(v.y) + fabsf(v.z) + fabsf(v.w);
            }
        }
        acc += (double)s;
    }
    #pragma unroll
    for (int o = 16; o > 0; o >>= 1) acc += __shfl_down_sync(0xffffffffu, acc, o);
    __shared__ double red[8];
    int lane = threadIdx.x & 31, wid = threadIdx.x >> 5;
    if (lane == 0) red[wid] = acc;
    __syncthreads();
    if (threadIdx.x == 0) {
        double t = 0.0;
        #pragma unroll
        for (int i = 0; i < 8; i++) t += red[i];
        atomicAdd(&g_abs_sum[slot], t);
    }
}

// ternary quantize: wq = sign(w) * (|w| > mean(|w|)*0.7), stored as fp16 {-1,0,1} (exact)
__global__ void quant_kernel(const float* __restrict__ w, f16* __restrict__ q,
                             long n, int slot) {
    float thr = (float)(g_abs_sum[slot] * (0.7 / (double)n));
    long i = (long)blockIdx.x * blockDim.x + threadIdx.x;
    long nv = n >> 2;
    if (i >= nv) return;
    float4 v = reinterpret_cast<const float4*>(w)[i];
    float vv[4] = {v.x, v.y, v.z, v.w};
    unsigned short r[4];
    #pragma unroll
    for (int j = 0; j < 4; j++) {
        float a = fabsf(vv[j]);
        r[j] = (a > thr) ? (vv[j] > 0.f ? (unsigned short)0x3C00u
                                        : (unsigned short)0xBC00u)
                         : (unsigned short)0u;   // fp16 +1 / -1 / 0
    }
    reinterpret_cast<ushort4*>(q)[i] = make_ushort4(r[0], r[1], r[2], r[3]);
}

// fp32 -> fp16 round
__global__ void tohalf_kernel(const float* __restrict__ x, f16* __restrict__ y, long n) {
    long i = (long)blockIdx.x * blockDim.x + threadIdx.x;
    long nv = n >> 2;
    if (i >= nv) return;
    float4 v = reinterpret_cast<const float4*>(x)[i];
    float vv[4] = {v.x, v.y, v.z, v.w};
    unsigned short r[4];
    #pragma unroll
    for (int j = 0; j < 4; j++) r[j] = __half_as_ushort(__float2half_rn(vv[j]));
    reinterpret_cast<ushort4*>(y)[i] = make_ushort4(r[0], r[1], r[2], r[3]);
}

// hidden = silu(gate) * up -> fp16 (clamped against fp16 overflow tail risk)
__global__ void swiglu_kernel(const float* __restrict__ gate, const float* __restrict__ up,
                              f16* __restrict__ h, long n) {
    long i = (long)blockIdx.x * blockDim.x + threadIdx.x;
    long nv = n >> 2;
    if (i >= nv) return;
    float4 g4 = reinterpret_cast<const float4*>(gate)[i];
    float4 u4 = reinterpret_cast<const float4*>(up)[i];
    float gg[4] = {g4.x, g4.y, g4.z, g4.w};
    float uu[4] = {u4.x, u4.y, u4.z, u4.w};
    unsigned short r[4];
    #pragma unroll
    for (int j = 0; j < 4; j++) {
        float g = gg[j];
        float s = 1.0f / (1.0f + expf(-g));
        float hv = g * s * uu[j];
        hv = fminf(fmaxf(hv, -65504.f), 65504.f);
        r[j] = __half_as_ushort(__float2half_rn(hv));
    }
    reinterpret_cast<ushort4*>(h)[i] = make_ushort4(r[0], r[1], r[2], r[3]);
}

// ---------------- GEMM: C[M,N] = A[M,K] * B[N,K]^T * scale[n], fp16 in / fp32 acc ----------------
static constexpr int BM = 128;
static constexpr int BN = 128;
static constexpr int BK = 32;
static constexpr int STAGES = 5;
static constexpr int SSTR = 40;                    // f16 per smem row (pad -> conflict-free)
static constexpr int ASTAGE = BM * SSTR;           // f16 elems per A stage
static constexpr int BSTAGE = BN * SSTR;
static constexpr int SMEM_BYTES = STAGES * (ASTAGE + BSTAGE) * 2;  // 102400

__device__ __forceinline__ void cp_async16(uint32_t saddr, const void* gptr) {
    asm volatile("cp.async.cg.shared.global [%0], [%1], 16;\n"
                 :: "r"(saddr), "l"(gptr) : "memory");
}
__device__ __forceinline__ void cp_commit() {
    asm volatile("cp.async.commit_group;\n" ::: "memory");
}
template <int N_>
__device__ __forceinline__ void cp_wait() {
    asm volatile("cp.async.wait_group %0;\n" :: "n"(N_) : "memory");
}
__device__ __forceinline__ void ldsm_x4(uint32_t (&r)[4], uint32_t saddr) {
    asm volatile("ldmatrix.sync.aligned.m8n8.x4.shared.b16 {%0,%1,%2,%3}, [%4];"
                 : "=r"(r[0]), "=r"(r[1]), "=r"(r[2]), "=r"(r[3]) : "r"(saddr));
}
__device__ __forceinline__ void ldsm_x2(uint32_t (&r)[2], uint32_t saddr) {
    asm volatile("ldmatrix.sync.aligned.m8n8.x2.shared.b16 {%0,%1}, [%2];"
                 : "=r"(r[0]), "=r"(r[1]) : "r"(saddr));
}

#define MMA_F16(d, a, b)                                                          \
    asm volatile(                                                                 \
        "mma.sync.aligned.m16n8k16.row.col.f32.f16.f16.f32 "                      \
        "{%0,%1,%2,%3},{%4,%5,%6,%7},{%8,%9},{%0,%1,%2,%3};"                      \
        : "+f"(d[0]), "+f"(d[1]), "+f"(d[2]), "+f"(d[3])                          \
        : "r"(a[0]), "r"(a[1]), "r"(a[2]), "r"(a[3]), "r"(b[0]), "r"(b[1]))

__global__ void __launch_bounds__(256)
gemm_f16(const f16* __restrict__ A, const f16* __restrict__ B,
         const float* __restrict__ scale, float* __restrict__ C,
         int M, int N, int K) {
    extern __shared__ f16 smem[];
    f16* sA = smem;
    f16* sB = smem + STAGES * ASTAGE;

    // tile swizzle for L2 reuse
    int grid_m = M / BM, grid_n = N / BN;
    const int GROUP = 8;
    int pid = blockIdx.x;
    int width = GROUP * grid_n;
    int group_id = pid / width;
    int group_size = min(grid_m - group_id * GROUP, GROUP);
    int pid_m = group_id * GROUP + (pid % group_size);
    int pid_n = (pid % width) / group_size;

    int tid = threadIdx.x;
    int lane = tid & 31, warp = tid >> 5;
    int warp_m = warp & 1, warp_n = warp >> 1;   // 2 x 4 warp grid, warp tile 64x32
    int gr = lane >> 2, tc = lane & 3;

    // cp.async mapping: thread -> row tid>>1, two 16B chunks at q=(tid&1)*2, +1
    int ldr = tid >> 1;
    int ldq = (tid & 1) * 2;

    const f16* gA = A + (size_t)pid_m * BM * K + (size_t)ldr * K + ldq * 8;
    const f16* gB = B + (size_t)pid_n * BN * K + (size_t)ldr * K + ldq * 8;

    uint32_t sAbase = (uint32_t)__cvta_generic_to_shared(sA);
    uint32_t sBbase = (uint32_t)__cvta_generic_to_shared(sB);
    uint32_t ldOff  = (uint32_t)(ldr * SSTR + ldq * 8) * 2;

    // ldmatrix per-lane offsets
    int aRow = (lane & 7) + ((lane >> 3) & 1) * 8;    // 0..15
    int aCol = (lane >> 4) * 8;                       // 0 or 8
    uint32_t aLaneOff = (uint32_t)(aRow * SSTR + aCol) * 2;
    int lb = lane & 15;
    uint32_t bLaneOff = (uint32_t)((lb & 7) * SSTR + (lb >> 3) * 8) * 2;

    auto load_stage = [&](int s, int kt) {
        int k0 = kt * BK;
        uint32_t dA = sAbase + (uint32_t)(s * ASTAGE) * 2 + ldOff;
        uint32_t dB = sBbase + (uint32_t)(s * BSTAGE) * 2 + ldOff;
        const f16* pA = gA + k0;
        const f16* pB = gB + k0;
        cp_async16(dA,      pA);
        cp_async16(dA + 16, pA + 8);
        cp_async16(dB,      pB);
        cp_async16(dB + 16, pB + 8);
    };

    float acc[4][4][4];
    #pragma unroll
    for (int i = 0; i < 4; i++)
        #pragma unroll
        for (int j = 0; j < 4; j++)
            #pragma unroll
            for (int k = 0; k < 4; k++) acc[i][j][k] = 0.f;

    int KT = K / BK;

    #pragma unroll
    for (int s = 0; s < STAGES - 1; ++s) {
        if (s < KT) load_stage(s, s);
        cp_commit();
    }

    for (int kt = 0; kt < KT; ++kt) {
        cp_wait<STAGES - 2>();
        __syncthreads();

        int nk = kt + STAGES - 1;
        if (nk < KT) load_stage(nk % STAGES, nk);
        cp_commit();

        int st = kt % STAGES;
        uint32_t aStage = sAbase + (uint32_t)(st * ASTAGE) * 2;
        uint32_t bStage = sBbase + (uint32_t)(st * BSTAGE) * 2;

        #pragma unroll
        for (int kc = 0; kc < 2; ++kc) {
            uint32_t a[4][4], b[4][2];
            #pragma unroll
            for (int ni = 0; ni < 4; ++ni)
                ldsm_x2(b[ni], bStage +
                        (uint32_t)((warp_n * 32 + ni * 8) * SSTR + kc * 16) * 2 + bLaneOff);
            #pragma unroll
            for (int mi = 0; mi < 4; ++mi)
                ldsm_x4(a[mi], aStage +
                        (uint32_t)((warp_m * 64 + mi * 16) * SSTR + kc * 16) * 2 + aLaneOff);
            #pragma unroll
            for (int mi = 0; mi < 4; ++mi)
                #pragma unroll
                for (int ni = 0; ni < 4; ++ni)
                    MMA_F16(acc[mi][ni], a[mi], b[ni]);
        }
    }

    // epilogue: C[m,n] = acc * scale[n]
    #pragma unroll
    for (int ni = 0; ni < 4; ++ni) {
        int n0 = pid_n * BN + warp_n * 32 + ni * 8 + tc * 2;
        float s0 = scale[n0], s1 = scale[n0 + 1];
        #pragma unroll
        for (int mi = 0; mi < 4; ++mi) {
            int m0 = pid_m * BM + warp_m * 64 + mi * 16 + gr;
            float2 v0 = make_float2(acc[mi][ni][0] * s0, acc[mi][ni][1] * s1);
            float2 v1 = make_float2(acc[mi][ni][2] * s0, acc[mi][ni][3] * s1);
            *reinterpret_cast<float2*>(&C[(size_t)m0 * N + n0]) = v0;
            *reinterpret_cast<float2*>(&C[(size_t)(m0 + 8) * N + n0]) = v1;
        }
    }
}

// ---------------- launcher ----------------
extern "C" void kernel_launch(void* const* d_in, const int* in_sizes, int n_in,
                              void* d_out, int out_size) {
    const float* x          = (const float*)d_in[0];
    const float* gate_w     = (const float*)d_in[1];
    const float* gate_scale = (const float*)d_in[2];
    const float* up_w       = (const float*)d_in[3];
    const float* up_scale   = (const float*)d_in[4];
    const float* down_w     = (const float*)d_in[5];
    const float* down_scale = (const float*)d_in[6];
    float* out = (float*)d_out;
    (void)in_sizes; (void)n_in; (void)out_size;

    void *p_wq_g, *p_wq_u, *p_wq_d, *p_x16, *p_gate, *p_up, *p_h16;
    cudaGetSymbolAddress(&p_wq_g, g_wq_gate);
    cudaGetSymbolAddress(&p_wq_u, g_wq_up);
    cudaGetSymbolAddress(&p_wq_d, g_wq_down);
    cudaGetSymbolAddress(&p_x16,  g_x16);
    cudaGetSymbolAddress(&p_gate, g_gate);
    cudaGetSymbolAddress(&p_up,   g_up);
    cudaGetSymbolAddress(&p_h16,  g_h16);

    cudaFuncSetAttribute(gemm_f16, cudaFuncAttributeMaxDynamicSharedMemorySize,
                         SMEM_BYTES);

    // 1) thresholds
    zero_sums_kernel<<<1, 32>>>();
    absum_kernel<<<2048, 256>>>(gate_w, NW, 0);
    absum_kernel<<<2048, 256>>>(up_w,   NW, 1);
    absum_kernel<<<2048, 256>>>(down_w, NW, 2);

    // 2) ternary-quantize weights into fp16 (exact {-1,0,1})
    unsigned qgrid = (unsigned)(NW / 4 / 256);
    quant_kernel<<<qgrid, 256>>>(gate_w, (f16*)p_wq_g, NW, 0);
    quant_kernel<<<qgrid, 256>>>(up_w,   (f16*)p_wq_u, NW, 1);
    quant_kernel<<<qgrid, 256>>>(down_w, (f16*)p_wq_d, NW, 2);

    // 3) activations -> fp16
    tohalf_kernel<<<(unsigned)(NX / 4 / 256), 256>>>(x, (f16*)p_x16, NX);

    // 4) gate / up GEMMs  (M=4096, N=16384, K=4096)
    unsigned grid1 = (unsigned)((MTOK / BM) * (HIDN / BN));
    gemm_f16<<<grid1, 256, SMEM_BYTES>>>((const f16*)p_x16, (const f16*)p_wq_g,
                                         gate_scale, (float*)p_gate, MTOK, HIDN, DIM);
    gemm_f16<<<grid1, 256, SMEM_BYTES>>>((const f16*)p_x16, (const f16*)p_wq_u,
                                         up_scale, (float*)p_up, MTOK, HIDN, DIM);

    // 5) silu(gate)*up -> fp16
    swiglu_kernel<<<(unsigned)(NH / 4 / 256), 256>>>((const float*)p_gate,
                                                     (const float*)p_up,
                                                     (f16*)p_h16, NH);

    // 6) down GEMM straight into d_out  (M=4096, N=4096, K=16384)
    unsigned grid2 = (unsigned)((MTOK / BM) * (DIM / BN));
    gemm_f16<<<grid2, 256, SMEM_BYTES>>>((const f16*)p_h16, (const f16*)p_wq_d,
                                         down_scale, out, MTOK, DIM, HIDN);
}

// round 14
// speedup vs baseline: 1.7208x; 1.1391x over previous
#include <cuda_runtime.h>
#include <cuda_fp16.h>
#include <cstdint>
#include <cstddef>

using f16 = __half;

// Problem constants (fixed by metadata)
static constexpr int  DIM  = 4096;
static constexpr int  HIDN = 16384;
static constexpr int  MTOK = 4096;                 // 2 * 2048 tokens
static constexpr long NW   = (long)DIM * HIDN;     // 67,108,864
static constexpr long NX   = (long)MTOK * DIM;     // 16,777,216
static constexpr long NH   = (long)MTOK * HIDN;    // 67,108,864

// ---------------- scratch (device globals: no cudaMalloc allowed) ----------------
__device__ double g_abs_sum[3];

__device__ __align__(16) f16   g_wq_gate[NW];
__device__ __align__(16) f16   g_wq_up[NW];
__device__ __align__(16) f16   g_wq_down[NW];
__device__ __align__(16) f16   g_x16[NX];
__device__ __align__(16) float g_gate[NH];
__device__ __align__(16) float g_up[NH];
__device__ __align__(16) f16   g_h16[NH];

// ---------------- small utility kernels ----------------
__global__ void zero_sums_kernel() {
    if (threadIdx.x < 3) g_abs_sum[threadIdx.x] = 0.0;
}

// abs-sum: fp32 inner chunks (32 elems), fp64 outer accumulation.
__global__ void absum_kernel(const float* __restrict__ w, long n, int slot) {
    long nv = n >> 2;
    long stride = (long)gridDim.x * blockDim.x;
    long i0 = (long)blockIdx.x * blockDim.x + threadIdx.x;
    double acc = 0.0;
    for (long base = i0; base < nv; base += stride * 8) {
        float s = 0.f;
        #pragma unroll
        for (int j = 0; j < 8; j++) {
            long i = base + (long)j * stride;
            if (i < nv) {
                float4 v = reinterpret_cast<const float4*>(w)[i];
                s += fabsf(v.x) + fabsf(v.y) + fabsf(v.z) + fabsf(v.w);
            }
        }
        acc += (double)s;
    }
    #pragma unroll
    for (int o = 16; o > 0; o >>= 1) acc += __shfl_down_sync(0xffffffffu, acc, o);
    __shared__ double red[8];
    int lane = threadIdx.x & 31, wid = threadIdx.x >> 5;
    if (lane == 0) red[wid] = acc;
    __syncthreads();
    if (threadIdx.x == 0) {
        double t = 0.0;
        #pragma unroll
        for (int i = 0; i < 8; i++) t += red[i];
        atomicAdd(&g_abs_sum[slot], t);
    }
}

// ternary quantize: wq = sign(w) * (|w| > mean(|w|)*0.7), stored as fp16 {-1,0,1} (exact)
__global__ void quant_kernel(const float* __restrict__ w, f16* __restrict__ q,
                             long n, int slot) {
    float thr = (float)(g_abs_sum[slot] * (0.7 / (double)n));
    long i = (long)blockIdx.x * blockDim.x + threadIdx.x;
    long nv = n >> 2;
    if (i >= nv) return;
    float4 v = reinterpret_cast<const float4*>(w)[i];
    float vv[4] = {v.x, v.y, v.z, v.w};
    unsigned short r[4];
    #pragma unroll
    for (int j = 0; j < 4; j++) {
        float a = fabsf(vv[j]);
        r[j] = (a > thr) ? (vv[j] > 0.f ? (unsigned short)0x3C00u
                                        : (unsigned short)0xBC00u)
                         : (unsigned short)0u;   // fp16 +1 / -1 / 0
    }
    reinterpret_cast<ushort4*>(q)[i] = make_ushort4(r[0], r[1], r[2], r[3]);
}

// fp32 -> fp16 round
__global__ void tohalf_kernel(const float* __restrict__ x, f16* __restrict__ y, long n) {
    long i = (long)blockIdx.x * blockDim.x + threadIdx.x;
    long nv = n >> 2;
    if (i >= nv) return;
    float4 v = reinterpret_cast<const float4*>(x)[i];
    float vv[4] = {v.x, v.y, v.z, v.w};
    unsigned short r[4];
    #pragma unroll
    for (int j = 0; j < 4; j++) r[j] = __half_as_ushort(__float2half_rn(vv[j]));
    reinterpret_cast<ushort4*>(y)[i] = make_ushort4(r[0], r[1], r[2], r[3]);
}

// hidden = silu(gate) * up -> fp16
__global__ void swiglu_kernel(const float* __restrict__ gate, const float* __restrict__ up,
                              f16* __restrict__ h, long n) {
    long i = (long)blockIdx.x * blockDim.x + threadIdx.x;
    long nv = n >> 2;
    if (i >= nv) return;
    float4 g4 = reinterpret_cast<const float4*>(gate)[i];
    float4 u4 = reinterpret_cast<const float4*>(up)[i];
    float gg[4] = {g4.x, g4.y, g4.z, g4.w};
    float uu[4] = {u4.x, u4.y, u4.z, u4.w};
    unsigned short r[4];
    #pragma unroll
    for (int j = 0; j < 4; j++) {
        float g = gg[j];
        float s = 1.0f / (1.0f + expf(-g));
        float hv = g * s * uu[j];
        hv = fminf(fmaxf(hv, -65504.f), 65504.f);
        r[j] = __half_as_ushort(__float2half_rn(hv));
    }
    reinterpret_cast<ushort4*>(h)[i] = make_ushort4(r[0], r[1], r[2], r[3]);
}

// ---------------- GEMM: C[M,N] = A[M,K] * B[N,K]^T * scale[n], fp16 in / fp32 acc ----------------
static constexpr int BM = 128;
static constexpr int BN = 128;
static constexpr int BK = 32;
static constexpr int STAGES = 5;
static constexpr int SSTR = 40;                    // f16 per smem row (pad -> conflict-free)
static constexpr int ASTAGE = BM * SSTR;           // f16 elems per A stage
static constexpr int BSTAGE = BN * SSTR;
static constexpr int SMEM_BYTES = STAGES * (ASTAGE + BSTAGE) * 2;  // 102400

__device__ __forceinline__ void cp_async16(uint32_t saddr, const void* gptr) {
    asm volatile("cp.async.cg.shared.global [%0], [%1], 16;\n"
                 :: "r"(saddr), "l"(gptr) : "memory");
}
__device__ __forceinline__ void cp_commit() {
    asm volatile("cp.async.commit_group;\n" ::: "memory");
}
template <int N_>
__device__ __forceinline__ void cp_wait() {
    asm volatile("cp.async.wait_group %0;\n" :: "n"(N_) : "memory");
}
__device__ __forceinline__ void ldsm_x4(uint32_t (&r)[4], uint32_t saddr) {
    asm volatile("ldmatrix.sync.aligned.m8n8.x4.shared.b16 {%0,%1,%2,%3}, [%4];"
                 : "=r"(r[0]), "=r"(r[1]), "=r"(r[2]), "=r"(r[3]) : "r"(saddr));
}
__device__ __forceinline__ void ldsm_x2(uint32_t (&r)[2], uint32_t saddr) {
    asm volatile("ldmatrix.sync.aligned.m8n8.x2.shared.b16 {%0,%1}, [%2];"
                 : "=r"(r[0]), "=r"(r[1]) : "r"(saddr));
}

#define MMA_F16(d, a, b)                                                          \
    asm volatile(                                                                 \
        "mma.sync.aligned.m16n8k16.row.col.f32.f16.f16.f32 "                      \
        "{%0,%1,%2,%3},{%4,%5,%6,%7},{%8,%9},{%0,%1,%2,%3};"                      \
        : "+f"(d[0]), "+f"(d[1]), "+f"(d[2]), "+f"(d[3])                          \
        : "r"(a[0]), "r"(a[1]), "r"(a[2]), "r"(a[3]), "r"(b[0]), "r"(b[1]))

__global__ void __launch_bounds__(256, 2)   // <<< the fix: force <=128 regs, 2 CTAs/SM
gemm_f16(const f16* __restrict__ A, const f16* __restrict__ B,
         const float* __restrict__ scale, float* __restrict__ C,
         int M, int N, int K) {
    extern __shared__ f16 smem[];
    f16* sA = smem;
    f16* sB = smem + STAGES * ASTAGE;

    // tile swizzle for L2 reuse
    int grid_m = M / BM, grid_n = N / BN;
    const int GROUP = 8;
    int pid = blockIdx.x;
    int width = GROUP * grid_n;
    int group_id = pid / width;
    int group_size = min(grid_m - group_id * GROUP, GROUP);
    int pid_m = group_id * GROUP + (pid % group_size);
    int pid_n = (pid % width) / group_size;

    int tid = threadIdx.x;
    int lane = tid & 31, warp = tid >> 5;
    int warp_m = warp & 1, warp_n = warp >> 1;   // 2 x 4 warp grid, warp tile 64x32
    int gr = lane >> 2, tc = lane & 3;

    // cp.async mapping: thread -> row tid>>1, two 16B chunks at q=(tid&1)*2, +1
    int ldr = tid >> 1;
    int ldq = (tid & 1) * 2;

    const f16* gA = A + (size_t)pid_m * BM * K + (size_t)ldr * K + ldq * 8;
    const f16* gB = B + (size_t)pid_n * BN * K + (size_t)ldr * K + ldq * 8;

    uint32_t sAbase = (uint32_t)__cvta_generic_to_shared(sA);
    uint32_t sBbase = (uint32_t)__cvta_generic_to_shared(sB);
    uint32_t ldOff  = (uint32_t)(ldr * SSTR + ldq * 8) * 2;

    // ldmatrix per-lane offsets
    int aRow = (lane & 7) + ((lane >> 3) & 1) * 8;    // 0..15
    int aCol = (lane >> 4) * 8;                       // 0 or 8
    uint32_t aLaneOff = (uint32_t)(aRow * SSTR + aCol) * 2;
    int lb = lane & 15;
    uint32_t bLaneOff = (uint32_t)((lb & 7) * SSTR + (lb >> 3) * 8) * 2;

    auto load_stage = [&](int s, int kt) {
        int k0 = kt * BK;
        uint32_t dA = sAbase + (uint32_t)(s * ASTAGE) * 2 + ldOff;
        uint32_t dB = sBbase + (uint32_t)(s * BSTAGE) * 2 + ldOff;
        const f16* pA = gA + k0;
        const f16* pB = gB + k0;
        cp_async16(dA,      pA);
        cp_async16(dA + 16, pA + 8);
        cp_async16(dB,      pB);
        cp_async16(dB + 16, pB + 8);
    };

    float acc[4][4][4];
    #pragma unroll
    for (int i = 0; i < 4; i++)
        #pragma unroll
        for (int j = 0; j < 4; j++)
            #pragma unroll
            for (int k = 0; k < 4; k++) acc[i][j][k] = 0.f;

    int KT = K / BK;

    #pragma unroll
    for (int s = 0; s < STAGES - 1; ++s) {
        if (s < KT) load_stage(s, s);
        cp_commit();
    }

    for (int kt = 0; kt < KT; ++kt) {
        cp_wait<STAGES - 2>();
        __syncthreads();

        int nk = kt + STAGES - 1;
        if (nk < KT) load_stage(nk % STAGES, nk);
        cp_commit();

        int st = kt % STAGES;
        uint32_t aStage = sAbase + (uint32_t)(st * ASTAGE) * 2;
        uint32_t bStage = sBbase + (uint32_t)(st * BSTAGE) * 2;

        #pragma unroll
        for (int kc = 0; kc < 2; ++kc) {
            uint32_t a[4][4], b[4][2];
            #pragma unroll
            for (int ni = 0; ni < 4; ++ni)
                ldsm_x2(b[ni], bStage +
                        (uint32_t)((warp_n * 32 + ni * 8) * SSTR + kc * 16) * 2 + bLaneOff);
            #pragma unroll
            for (int mi = 0; mi < 4; ++mi)
                ldsm_x4(a[mi], aStage +
                        (uint32_t)((warp_m * 64 + mi * 16) * SSTR + kc * 16) * 2 + aLaneOff);
            #pragma unroll
            for (int mi = 0; mi < 4; ++mi)
                #pragma unroll
                for (int ni = 0; ni < 4; ++ni)
                    MMA_F16(acc[mi][ni], a[mi], b[ni]);
        }
    }

    // epilogue: C[m,n] = acc * scale[n]
    #pragma unroll
    for (int ni = 0; ni < 4; ++ni) {
        int n0 = pid_n * BN + warp_n * 32 + ni * 8 + tc * 2;
        float s0 = scale[n0], s1 = scale[n0 + 1];
        #pragma unroll
        for (int mi = 0; mi < 4; ++mi) {
            int m0 = pid_m * BM + warp_m * 64 + mi * 16 + gr;
            float2 v0 = make_float2(acc[mi][ni][0] * s0, acc[mi][ni][1] * s1);
            float2 v1 = make_float2(acc[mi][ni][2] * s0, acc[mi][ni][3] * s1);
            *reinterpret_cast<float2*>(&C[(size_t)m0 * N + n0]) = v0;
            *reinterpret_cast<float2*>(&C[(size_t)(m0 + 8) * N + n0]) = v1;
        }
    }
}

// ---------------- launcher ----------------
extern "C" void kernel_launch(void* const* d_in, const int* in_sizes, int n_in,
                              void* d_out, int out_size) {
    const float* x          = (const float*)d_in[0];
    const float* gate_w     = (const float*)d_in[1];
    const float* gate_scale = (const float*)d_in[2];
    const float* up_w       = (const float*)d_in[3];
    const float* up_scale   = (const float*)d_in[4];
    const float* down_w     = (const float*)d_in[5];
    const float* down_scale = (const float*)d_in[6];
    float* out = (float*)d_out;
    (void)in_sizes; (void)n_in; (void)out_size;

    void *p_wq_g, *p_wq_u, *p_wq_d, *p_x16, *p_gate, *p_up, *p_h16;
    cudaGetSymbolAddress(&p_wq_g, g_wq_gate);
    cudaGetSymbolAddress(&p_wq_u, g_wq_up);
    cudaGetSymbolAddress(&p_wq_d, g_wq_down);
    cudaGetSymbolAddress(&p_x16,  g_x16);
    cudaGetSymbolAddress(&p_gate, g_gate);
    cudaGetSymbolAddress(&p_up,   g_up);
    cudaGetSymbolAddress(&p_h16,  g_h16);

    cudaFuncSetAttribute(gemm_f16, cudaFuncAttributeMaxDynamicSharedMemorySize,
                         SMEM_BYTES);

    // 1) thresholds
    zero_sums_kernel<<<1, 32>>>();
    absum_kernel<<<2048, 256>>>(gate_w, NW, 0);
    absum_kernel<<<2048, 256>>>(up_w,   NW, 1);
    absum_kernel<<<2048, 256>>>(down_w, NW, 2);

    // 2) ternary-quantize weights into fp16 (exact {-1,0,1})
    unsigned qgrid = (unsigned)(NW / 4 / 256);
    quant_kernel<<<qgrid, 256>>>(gate_w, (f16*)p_wq_g, NW, 0);
    quant_kernel<<<qgrid, 256>>>(up_w,   (f16*)p_wq_u, NW, 1);
    quant_kernel<<<qgrid, 256>>>(down_w, (f16*)p_wq_d, NW, 2);

    // 3) activations -> fp16
    tohalf_kernel<<<(unsigned)(NX / 4 / 256), 256>>>(x, (f16*)p_x16, NX);

    // 4) gate / up GEMMs  (M=4096, N=16384, K=4096)
    unsigned grid1 = (unsigned)((MTOK / BM) * (HIDN / BN));
    gemm_f16<<<grid1, 256, SMEM_BYTES>>>((const f16*)p_x16, (const f16*)p_wq_g,
                                         gate_scale, (float*)p_gate, MTOK, HIDN, DIM);
    gemm_f16<<<grid1, 256, SMEM_BYTES>>>((const f16*)p_x16, (const f16*)p_wq_u,
                                         up_scale, (float*)p_up, MTOK, HIDN, DIM);

    // 5) silu(gate)*up -> fp16
    swiglu_kernel<<<(unsigned)(NH / 4 / 256), 256>>>((const float*)p_gate,
                                                     (const float*)p_up,
                                                     (f16*)p_h16, NH);

    // 6) down GEMM straight into d_out  (M=4096, N=4096, K=16384)
    unsigned grid2 = (unsigned)((MTOK / BM) * (DIM / BN));
    gemm_f16<<<grid2, 256, SMEM_BYTES>>>((const f16*)p_h16, (const f16*)p_wq_d,
                                         down_scale, out, MTOK, DIM, HIDN);
}